// round 5
// baseline (speedup 1.0000x reference)
#include <cuda_runtime.h>
#include <cstdint>

// Problem constants (fixed by the reference)
#define EMB_D   64
#define HID     128
#define KDIM    128     // 2*EMB_D
#define TM      128     // batch rows per block
#define NTHR    256
#define XP      136     // xT pitch in floats (16B-aligned: 136*4=544)

// ---------------- f32x2 helpers (Blackwell packed fp32) ----------------
__device__ __forceinline__ unsigned long long f2pk(float lo, float hi) {
    unsigned long long r;
    asm("mov.b64 %0, {%1, %2};" : "=l"(r) : "f"(lo), "f"(hi));
    return r;
}
__device__ __forceinline__ void f2up(unsigned long long v, float& lo, float& hi) {
    asm("mov.b64 {%0, %1}, %2;" : "=f"(lo), "=f"(hi) : "l"(v));
}
__device__ __forceinline__ unsigned long long f2fma(unsigned long long a,
                                                    unsigned long long b,
                                                    unsigned long long c) {
    unsigned long long d;
    asm("fma.rn.f32x2 %0, %1, %2, %3;" : "=l"(d) : "l"(a), "l"(b), "l"(c));
    return d;
}
__device__ __forceinline__ unsigned long long f2add(unsigned long long a,
                                                    unsigned long long b) {
    unsigned long long d;
    asm("add.rn.f32x2 %0, %1, %2;" : "=l"(d) : "l"(a), "l"(b));
    return d;
}

// Smem layout (floats):
//   w1d : KDIM * 256          (duplicated weights: w1d[k*256+2j] = w1d[k*256+2j+1] = w1[j][k])
//   xT  : KDIM * XP           (transposed gathered inputs: xT[k*XP + row])
//   b1s : HID
//   w2s : HID
//   uidx/iidx : TM ints each
#define SM_W1D_F   (KDIM * 256)
#define SM_XT_F    (KDIM * XP)
#define SM_FLOATS  (SM_W1D_F + SM_XT_F + 2 * HID)
#define SM_BYTES   (SM_FLOATS * sizeof(float) + 2 * TM * sizeof(int))

extern "C" __global__ void __launch_bounds__(NTHR, 1)
mf_fused_kernel(const int* __restrict__ users,
                const int* __restrict__ items,
                const float* __restrict__ user_emb,
                const float* __restrict__ item_emb,
                const float* __restrict__ user_bias,
                const float* __restrict__ item_bias,
                const float* __restrict__ global_bias,
                const float* __restrict__ w1,
                const float* __restrict__ b1,
                const float* __restrict__ w2,
                const float* __restrict__ b2,
                float* __restrict__ out,
                int B)
{
    extern __shared__ float sm[];
    float* w1d = sm;
    float* xT  = sm + SM_W1D_F;
    float* b1s = xT + SM_XT_F;
    float* w2s = b1s + HID;
    int*   uidx = (int*)(w2s + HID);
    int*   iidx = uidx + TM;

    const int tid  = threadIdx.x;
    const int base = blockIdx.x * TM;

    // ---- small params + indices into smem ----
    if (tid < HID) { b1s[tid] = b1[tid]; w2s[tid] = w2[tid]; }
    if (tid < TM) {
        int row = base + tid;
        int u = 0, it = 0;
        if (row < B) { u = users[row]; it = items[row]; }
        uidx[tid] = u;
        iidx[tid] = it;
    }

    // ---- stage w1 duplicated+transposed: w1 is [HID][KDIM] row-major ----
    // 4096 float4 reads total, 16 per thread
    for (int v = tid; v < (HID * KDIM) / 4; v += NTHR) {
        int j  = v >> 5;            // 0..127
        int k4 = (v & 31) << 2;     // 0,4,...,124
        float4 w = *(const float4*)(w1 + j * KDIM + k4);
        float* p0 = w1d + (k4 + 0) * 256 + 2 * j;
        float* p1 = w1d + (k4 + 1) * 256 + 2 * j;
        float* p2 = w1d + (k4 + 2) * 256 + 2 * j;
        float* p3 = w1d + (k4 + 3) * 256 + 2 * j;
        p0[0] = w.x; p0[1] = w.x;
        p1[0] = w.y; p1[1] = w.y;
        p2[0] = w.z; p2[1] = w.z;
        p3[0] = w.w; p3[1] = w.w;
    }

    // ---- gather embeddings into transposed smem tile ----
    // thread t: row = t/2, half = t&1 (0=user -> k 0..63, 1=item -> k 64..127)
    {
        int r    = tid >> 1;
        int half = tid & 1;
        int row  = base + r;
        const float* tbl = half ? item_emb : user_emb;
        int idx = 0;
        if (row < B) idx = half ? items[row] : users[row];
        const float4* src = (const float4*)(tbl + (size_t)idx * EMB_D);
        int kb = half * EMB_D;
        #pragma unroll
        for (int i = 0; i < EMB_D / 4; i++) {
            float4 v = src[i];
            int k = kb + 4 * i;
            xT[(k + 0) * XP + r] = v.x;
            xT[(k + 1) * XP + r] = v.y;
            xT[(k + 2) * XP + r] = v.z;
            xT[(k + 3) * XP + r] = v.w;
        }
    }
    __syncthreads();

    // ---- GEMM mainloop ----
    // thread (tx, ty): tx = tid&15 owns hidden units j = tx + 16*m (m=0..7)
    //                  ty = tid>>4 owns rows r0..r0+7 as 4 f32x2 pairs
    const int tx = tid & 15;
    const int ty = tid >> 4;
    const int r0 = ty * 8;

    unsigned long long acc[8][4];
    #pragma unroll
    for (int m = 0; m < 8; m++)
        #pragma unroll
        for (int p = 0; p < 4; p++)
            acc[m][p] = 0ull;

    const float* wbase = w1d + 2 * tx;
    const float* xbase = xT + r0;

    #pragma unroll 2
    for (int k = 0; k < KDIM; k++) {
        const float* wrow = wbase + k * 256;
        const float* xrow = xbase + k * XP;
        unsigned long long wv[8], xv[4];
        #pragma unroll
        for (int m = 0; m < 8; m++)
            wv[m] = *(const unsigned long long*)(wrow + 32 * m);
        #pragma unroll
        for (int p = 0; p < 4; p++)
            xv[p] = *(const unsigned long long*)(xrow + 2 * p);
        #pragma unroll
        for (int m = 0; m < 8; m++)
            #pragma unroll
            for (int p = 0; p < 4; p++)
                acc[m][p] = f2fma(wv[m], xv[p], acc[m][p]);
    }

    // ---- epilogue: relu + w2 contraction (per-thread over its 8 hidden units) ----
    unsigned long long s[4] = {0ull, 0ull, 0ull, 0ull};
    #pragma unroll
    for (int m = 0; m < 8; m++) {
        int j = tx + 16 * m;
        float bj = b1s[j];
        float wj = w2s[j];
        #pragma unroll
        for (int p = 0; p < 4; p++) {
            float lo, hi;
            f2up(acc[m][p], lo, hi);
            lo = fmaxf(lo + bj, 0.0f) * wj;
            hi = fmaxf(hi + bj, 0.0f) * wj;
            s[p] = f2add(s[p], f2pk(lo, hi));
        }
    }

    // ---- fold dot(u,v) partials into the same reduction: tx covers k in [4tx, 4tx+4) ----
    #pragma unroll
    for (int kk = 0; kk < 4; kk++) {
        int k = tx * 4 + kk;
        const float* xu = xT + k * XP + r0;
        const float* xi = xT + (k + EMB_D) * XP + r0;
        #pragma unroll
        for (int p = 0; p < 4; p++) {
            unsigned long long u = *(const unsigned long long*)(xu + 2 * p);
            unsigned long long v = *(const unsigned long long*)(xi + 2 * p);
            s[p] = f2fma(u, v, s[p]);
        }
    }

    // ---- reduce across the 16 tx lanes (xor stays within each 16-lane half) ----
    #pragma unroll
    for (int off = 1; off < 16; off <<= 1) {
        #pragma unroll
        for (int p = 0; p < 4; p++) {
            unsigned long long o = __shfl_xor_sync(0xFFFFFFFFu, s[p], off);
            s[p] = f2add(s[p], o);
        }
    }

    // ---- tx==0 of each row group writes 8 rows ----
    if (tx == 0) {
        float gb = global_bias[0] + b2[0];
        #pragma unroll
        for (int p = 0; p < 4; p++) {
            float lo, hi;
            f2up(s[p], lo, hi);
            int r = r0 + 2 * p;
            if (base + r < B)
                out[base + r]     = lo + gb + user_bias[uidx[r]]     + item_bias[iidx[r]];
            if (base + r + 1 < B)
                out[base + r + 1] = hi + gb + user_bias[uidx[r + 1]] + item_bias[iidx[r + 1]];
        }
    }
}

extern "C" void kernel_launch(void* const* d_in, const int* in_sizes, int n_in,
                              void* d_out, int out_size)
{
    const int*   users       = (const int*)  d_in[0];
    const int*   items       = (const int*)  d_in[1];
    const float* user_emb    = (const float*)d_in[2];
    const float* item_emb    = (const float*)d_in[3];
    const float* user_bias   = (const float*)d_in[4];
    const float* item_bias   = (const float*)d_in[5];
    const float* global_bias = (const float*)d_in[6];
    const float* w1          = (const float*)d_in[7];
    const float* b1          = (const float*)d_in[8];
    const float* w2          = (const float*)d_in[9];
    const float* b2          = (const float*)d_in[10];
    float*       out         = (float*)d_out;

    int B = in_sizes[0];
    int grid = (B + TM - 1) / TM;

    cudaFuncSetAttribute(mf_fused_kernel,
                         cudaFuncAttributeMaxDynamicSharedMemorySize,
                         (int)SM_BYTES);

    mf_fused_kernel<<<grid, NTHR, SM_BYTES>>>(
        users, items, user_emb, item_emb, user_bias, item_bias, global_bias,
        w1, b1, w2, b2, out, B);
}

// round 7
// speedup vs baseline: 1.2912x; 1.2912x over previous
#include <cuda_runtime.h>
#include <cstdint>

// Problem constants (fixed by the reference)
#define EMB_D   64
#define HID     128
#define KDIM    128
#define TM      64      // batch rows per block -> grid = 256 covers all 148 SMs
#define NTHR    128
#define WP      130     // row pitch (floats) for w1s and xT: even (8B align), 130 mod 32 = 2 -> conflict-free

typedef unsigned long long u64;

// ---------------- f32x2 helpers (Blackwell packed fp32) ----------------
__device__ __forceinline__ void f2up(u64 v, float& lo, float& hi) {
    asm("mov.b64 {%0, %1}, %2;" : "=f"(lo), "=f"(hi) : "l"(v));
}
__device__ __forceinline__ u64 f2fma(u64 a, u64 b, u64 c) {
    u64 d;
    asm("fma.rn.f32x2 %0, %1, %2, %3;" : "=l"(d) : "l"(a), "l"(b), "l"(c));
    return d;
}

// Smem layout (floats):
//   w1s : HID * WP      transposed weights, w1s[j*WP + k] = w1[j][k]   (16640 f)
//   xT  : TM  * WP      gathered inputs row-major, xT[r*WP + k]        ( 8320 f)
//   b1s : HID, w2s : HID, bsu : TM, bsi : TM
#define SM_W1S_F  (HID * WP)
#define SM_XT_F   (TM * WP)
#define SM_FLOATS (SM_W1S_F + SM_XT_F + 2 * HID + 2 * TM)
#define SM_BYTES  (SM_FLOATS * sizeof(float))

extern "C" __global__ void __launch_bounds__(NTHR, 2)
mf_fused_kernel(const int* __restrict__ users,
                const int* __restrict__ items,
                const float* __restrict__ user_emb,
                const float* __restrict__ item_emb,
                const float* __restrict__ user_bias,
                const float* __restrict__ item_bias,
                const float* __restrict__ global_bias,
                const float* __restrict__ w1,
                const float* __restrict__ b1,
                const float* __restrict__ w2,
                const float* __restrict__ b2,
                float* __restrict__ out,
                int B)
{
    extern __shared__ float sm[];
    float* w1s = sm;
    float* xT  = sm + SM_W1S_F;
    float* b1s = xT + SM_XT_F;
    float* w2s = b1s + HID;
    float* bsu = w2s + HID;
    float* bsi = bsu + TM;

    const int tid  = threadIdx.x;
    const int base = blockIdx.x * TM;

    // ---- gather embeddings + per-row biases into smem ----
    // thread t: row r = t/2, half = t&1 (0 = user -> k[0,64), 1 = item -> k[64,128))
    {
        int r    = tid >> 1;
        int half = tid & 1;
        int row  = base + r;
        int idx  = 0;
        if (row < B) idx = half ? items[row] : users[row];
        const float4* src = (const float4*)((half ? item_emb : user_emb)
                                            + (size_t)idx * EMB_D);
        float* dst = xT + r * WP + half * EMB_D;   // 8B-aligned (r*WP even, 64*half even)
        #pragma unroll
        for (int i = 0; i < EMB_D / 4; i++) {
            float4 v = src[i];
            ((float2*)dst)[2 * i]     = make_float2(v.x, v.y);
            ((float2*)dst)[2 * i + 1] = make_float2(v.z, v.w);
        }
        float bv = 0.0f;
        if (row < B) bv = half ? item_bias[idx] : user_bias[idx];
        (half ? bsi : bsu)[r] = bv;
    }

    // ---- stage w1 (row-major [HID][KDIM]) into padded rows, float2 granularity ----
    // store addr = j*WP + 2*k2 : warp lanes consecutive k2 -> contiguous, conflict-free
    {
        const float2* w1v = (const float2*)w1;
        #pragma unroll
        for (int i = tid; i < (HID * KDIM) / 2; i += NTHR) {
            int j  = i >> 6;      // 64 float2 per source row
            int k2 = i & 63;
            *(float2*)(w1s + j * WP + 2 * k2) = w1v[i];
        }
    }
    b1s[tid] = b1[tid];
    w2s[tid] = w2[tid];
    __syncthreads();

    // ---- GEMM mainloop: K split into (even,odd) halves of each f32x2 ----
    // tx = tid&15 owns hidden units j = tx + 16m (m=0..7)
    // ty = tid>>4 owns rows r = 8*ty .. 8*ty+7
    const int tx = tid & 15;
    const int ty = tid >> 4;
    const float* wB = w1s + tx * WP;
    const float* xB = xT + (ty * 8) * WP;

    u64 acc[8][8];
    #pragma unroll
    for (int m = 0; m < 8; m++)
        #pragma unroll
        for (int i = 0; i < 8; i++)
            acc[m][i] = 0ull;

    #pragma unroll 2
    for (int k = 0; k < KDIM; k += 2) {
        u64 wv[8], xv[8];
        #pragma unroll
        for (int m = 0; m < 8; m++)
            wv[m] = *(const u64*)(wB + m * (16 * WP) + k);   // (w[j][k], w[j][k+1])
        #pragma unroll
        for (int i = 0; i < 8; i++)
            xv[i] = *(const u64*)(xB + i * WP + k);          // (x[r][k], x[r][k+1])
        #pragma unroll
        for (int m = 0; m < 8; m++)
            #pragma unroll
            for (int i = 0; i < 8; i++)
                acc[m][i] = f2fma(wv[m], xv[i], acc[m][i]);
    }

    // ---- epilogue ----
    // dot(u,v) partials: tx covers k in [4tx, 4tx+4) as two k-pairs
    float s[8];
    {
        const int k0 = 4 * tx;
        #pragma unroll
        for (int i = 0; i < 8; i++) {
            const float* xr = xB + i * WP;
            u64 p = f2fma(*(const u64*)(xr + k0),
                          *(const u64*)(xr + EMB_D + k0),
                    f2fma(*(const u64*)(xr + k0 + 2),
                          *(const u64*)(xr + EMB_D + k0 + 2), 0ull));
            float lo, hi; f2up(p, lo, hi);
            s[i] = lo + hi;
        }
    }

    // relu + w2 contraction: sum the (even,odd) K halves BEFORE the relu
    #pragma unroll
    for (int m = 0; m < 8; m++) {
        int j   = tx + 16 * m;
        float bj = b1s[j];
        float wj = w2s[j];
        #pragma unroll
        for (int i = 0; i < 8; i++) {
            float lo, hi; f2up(acc[m][i], lo, hi);
            float h = lo + hi + bj;
            s[i] += fmaxf(h, 0.0f) * wj;
        }
    }

    // reduce across the 16 tx lanes (xor < 16 stays within each half-warp)
    #pragma unroll
    for (int off = 1; off < 16; off <<= 1)
        #pragma unroll
        for (int i = 0; i < 8; i++)
            s[i] += __shfl_xor_sync(0xFFFFFFFFu, s[i], off);

    // tx == 0 of each row group writes its 8 rows
    if (tx == 0) {
        float gb = global_bias[0] + b2[0];
        #pragma unroll
        for (int i = 0; i < 8; i++) {
            int r   = ty * 8 + i;
            int row = base + r;
            if (row < B)
                out[row] = s[i] + gb + bsu[r] + bsi[r];
        }
    }
}

extern "C" void kernel_launch(void* const* d_in, const int* in_sizes, int n_in,
                              void* d_out, int out_size)
{
    const int*   users       = (const int*)  d_in[0];
    const int*   items       = (const int*)  d_in[1];
    const float* user_emb    = (const float*)d_in[2];
    const float* item_emb    = (const float*)d_in[3];
    const float* user_bias   = (const float*)d_in[4];
    const float* item_bias   = (const float*)d_in[5];
    const float* global_bias = (const float*)d_in[6];
    const float* w1          = (const float*)d_in[7];
    const float* b1          = (const float*)d_in[8];
    const float* w2          = (const float*)d_in[9];
    const float* b2          = (const float*)d_in[10];
    float*       out         = (float*)d_out;

    int B = in_sizes[0];
    int grid = (B + TM - 1) / TM;   // 256 for B=16384

    cudaFuncSetAttribute(mf_fused_kernel,
                         cudaFuncAttributeMaxDynamicSharedMemorySize,
                         (int)SM_BYTES);

    mf_fused_kernel<<<grid, NTHR, SM_BYTES>>>(
        users, items, user_emb, item_emb, user_bias, item_bias, global_bias,
        w1, b1, w2, b2, out, B);
}